// round 14
// baseline (speedup 1.0000x reference)
#include <cuda_runtime.h>
#include <cuda_bf16.h>
#include <cuda_fp16.h>
#include <math.h>
#include <stdint.h>

#define N_ 1024
#define H_ 1024
#define B_ 64
#define T_ 256
#define BT_ (B_*T_)
#define HID_ 512

typedef __nv_bfloat16 bf16;

// ---------------- scratch (static device globals; no allocation) ----------------
__device__ __half g_hA16[BT_*H_];                  // h_time fp16
__device__ float g_hgate[B_*H_];
__device__ bf16  g_hgHi[128*H_];                   // h_gate bf16, padded to 128 rows
__device__ float g_hmean[H_];
__device__ bf16  g_Ehi[N_*H_];
__device__ float g_S[N_*N_];
__device__ float g_rowsum[N_];                     // stores 1/(rowsum+1e-6)
__device__ bf16  g_G1h[HID_*H_];                   // gate_W1^T bf16
__device__ bf16  g_G2h[N_*HID_];                   // gate_W2^T bf16
__device__ bf16  g_hidh[128*HID_];
__device__ float g_gmean[N_];
__device__ __half g_Am16h[N_*N_];                  // A_base fp16 (gmean deferred)
__device__ __half g_W116[H_*N_];                   // h2n_W fp16
__device__ __half g_W2t16[H_*N_];                  // n2h_W^T fp16
__device__ __half g_P16h[H_*N_], g_P16l[H_*N_];    // P fp16 hi/lo (gmean applied)
__device__ __half g_M16h[H_*H_];                   // McombT fp16
__device__ float g_zb[3*1024*1024];                // partials: S tiles [0,144*16384) ; gate1 at ZBG_OFF; P/M slabs
__device__ float g_u[N_];                          // ub[m] = <Abase[m],b1>
__device__ float g_cvec[H_];
__device__ __half g_msg16[BT_*H_];
__device__ unsigned int g_cnt[128];                // fgemm row-block completion counters

#define ZBG_OFF (144 * 16384)                      // gate1 partial region (4 x 65536 floats)

// ---------------- helpers ----------------
__device__ __forceinline__ unsigned short hfbits(__half x) {
    return *reinterpret_cast<unsigned short*>(&x);
}
__device__ __forceinline__ uint32_t smem_u32(const void* p) {
    uint32_t a;
    asm("{ .reg .u64 t; cvta.to.shared.u64 t, %1; cvt.u32.u64 %0, t; }" : "=r"(a) : "l"(p));
    return a;
}
__device__ __forceinline__ uint32_t swz(uint32_t off) {
    return off ^ ((off >> 3) & 0x70);
}
#define CP_COMMIT() asm volatile("cp.async.commit_group;" ::: "memory")

__device__ __forceinline__ void ldsm4(uint32_t (&r)[4], uint32_t addr) {
    asm volatile("ldmatrix.sync.aligned.m8n8.x4.shared.b16 {%0,%1,%2,%3}, [%4];"
        : "=r"(r[0]), "=r"(r[1]), "=r"(r[2]), "=r"(r[3]) : "r"(addr));
}
__device__ __forceinline__ void mma_bf(float* c, const uint32_t* a, uint32_t b0, uint32_t b1) {
    asm volatile("mma.sync.aligned.m16n8k16.row.col.f32.bf16.bf16.f32 "
        "{%0,%1,%2,%3}, {%4,%5,%6,%7}, {%8,%9}, {%0,%1,%2,%3};"
        : "+f"(c[0]), "+f"(c[1]), "+f"(c[2]), "+f"(c[3])
        : "r"(a[0]), "r"(a[1]), "r"(a[2]), "r"(a[3]), "r"(b0), "r"(b1));
}
__device__ __forceinline__ void mma_fp(float* c, const uint32_t* a, uint32_t b0, uint32_t b1) {
    asm volatile("mma.sync.aligned.m16n8k16.row.col.f32.f16.f16.f32 "
        "{%0,%1,%2,%3}, {%4,%5,%6,%7}, {%8,%9}, {%0,%1,%2,%3};"
        : "+f"(c[0]), "+f"(c[1]), "+f"(c[2]), "+f"(c[3])
        : "r"(a[0]), "r"(a[1]), "r"(a[2]), "r"(a[3]), "r"(b0), "r"(b1));
}

// load one 128row x 64col 16-bit tile (SW128 swizzled, 128B/row); 256 threads
__device__ __forceinline__ void ld_tile(uint32_t sdst, const void* __restrict__ g,
                                        int row0, int K, int kc, int tid) {
    const int row = tid >> 1, half = tid & 1;
    const char* src = (const char*)g + (((size_t)(row0 + row) * K + (kc << 6)) << 1) + half * 64;
    uint32_t rb = (uint32_t)row * 128 + (uint32_t)half * 64;
    #pragma unroll
    for (int j = 0; j < 4; j++) {
        uint32_t sw = swz(rb + (j << 4));
        asm volatile("cp.async.cg.shared.global [%0], [%1], 16;"
            :: "r"(sdst + sw), "l"(src + (j << 4)));
    }
}

#define TILE_B 16384
#define BUF_B  65536
#define GEMM_SMEM (1024 + 2 * BUF_B)
#define MEGA_SBUF 32768
#define MEGA_SMEM (1024 + 2 * MEGA_SBUF)

// ---------------- k_mega: fused S (36 tiles x split-K4) + gate1 (4 tiles x split-K4) ----------------
// grid (52, 1, 4). bx<36: S tile; bx>=36 && bz==0: gate1 subtile. Packed 2-tile buffers, 2 CTAs/SM.
__global__ __launch_bounds__(256, 2) void k_mega() {
    extern __shared__ __align__(1024) char smem[];
    uint32_t sb = smem_u32(smem);
    const int tid = threadIdx.x;
    const int wid = tid >> 5, lane = tid & 31;
    const int wm = wid >> 1, wn = wid & 1;

    const void *A, *B;
    int arow0, brow0, NKp, kc0, ostride, ocol0;
    float* dst;
    if (blockIdx.x < 36) {
        int t = blockIdx.x, i = 0;
        while (t >= 8 - i) { t -= 8 - i; i++; }
        A = g_Ehi; B = g_Ehi;
        arow0 = i * 128; brow0 = (i + t) * 128;
        NKp = 4; kc0 = blockIdx.z * 4;
        dst = g_zb + ((size_t)blockIdx.z * 36 + blockIdx.x) * 16384;
        ostride = 128; ocol0 = 0;
    } else {
        if (blockIdx.z) return;
        int idx = blockIdx.x - 36, gx = idx & 3, gz = idx >> 2;
        A = g_hgHi; B = g_G1h;
        arow0 = 0; brow0 = gx * 128;
        NKp = 4; kc0 = gz * 4;
        dst = g_zb + ZBG_OFF + (size_t)gz * 65536;
        ostride = 512; ocol0 = gx * 128;
    }

    const uint32_t T0 = sb + 1024;
    float acc[2][8][4];
    #pragma unroll
    for (int i = 0; i < 2; i++)
        #pragma unroll
        for (int j = 0; j < 8; j++)
            #pragma unroll
            for (int l = 0; l < 4; l++) acc[i][j][l] = 0.f;

    const int mi = lane >> 3, li = lane & 7;
    const int rowoff = (mi & 1) * 8 + li;
    const int coloff = (mi >> 1) * 16;

    ld_tile(T0, A, arow0, 1024, kc0, tid);
    ld_tile(T0 + TILE_B, B, brow0, 1024, kc0, tid);
    CP_COMMIT();

    for (int i = 0; i < NKp; i++) {
        const int cur = i & 1;
        if (i + 1 < NKp) {
            uint32_t nb = T0 + (cur ^ 1) * MEGA_SBUF;
            ld_tile(nb, A, arow0, 1024, kc0 + i + 1, tid);
            ld_tile(nb + TILE_B, B, brow0, 1024, kc0 + i + 1, tid);
            CP_COMMIT();
            asm volatile("cp.async.wait_group 1;" ::: "memory");
        } else {
            asm volatile("cp.async.wait_group 0;" ::: "memory");
        }
        __syncthreads();

        const uint32_t Ah = T0 + cur * MEGA_SBUF;
        const uint32_t Bh = Ah + TILE_B;

        #pragma unroll
        for (int ks = 0; ks < 4; ks++) {
            const int kb = ks * 32;
            uint32_t ahi[2][4];
            #pragma unroll
            for (int mt = 0; mt < 2; mt++) {
                uint32_t ra = swz((uint32_t)(wm * 32 + mt * 16 + rowoff) * 128 + kb + coloff);
                ldsm4(ahi[mt], Ah + ra);
            }
            #pragma unroll
            for (int g = 0; g < 4; g++) {
                uint32_t rb = swz((uint32_t)(wn * 64 + g * 16 + rowoff) * 128 + kb + coloff);
                uint32_t bh[4];
                ldsm4(bh, Bh + rb);
                #pragma unroll
                for (int mt = 0; mt < 2; mt++) {
                    #pragma unroll
                    for (int sub = 0; sub < 2; sub++) {
                        mma_bf(acc[mt][g * 2 + sub], ahi[mt], bh[sub], bh[2 + sub]);
                    }
                }
            }
        }
        __syncthreads();
    }

    #pragma unroll
    for (int mt = 0; mt < 2; mt++) {
        #pragma unroll
        for (int nt = 0; nt < 8; nt++) {
            const int rl = wm * 32 + mt * 16 + (lane >> 2);
            const int cl = wn * 64 + nt * 8 + (lane & 3) * 2;
            *(float2*)(dst + rl * ostride + ocol0 + cl)       = make_float2(acc[mt][nt][0], acc[mt][nt][1]);
            *(float2*)(dst + (rl + 8) * ostride + ocol0 + cl) = make_float2(acc[mt][nt][2], acc[mt][nt][3]);
        }
    }
}

// ---------------- k_mega2: P GEMM single-pass (128 CTAs) + gate2 (8) + ub (8); 2-tile packed ----------------
__global__ __launch_bounds__(256, 2) void k_mega2(const float* __restrict__ gb2,
                                                  const float* __restrict__ hb1) {
    extern __shared__ __align__(1024) char smem[];
    uint32_t sb = smem_u32(smem);
    const int tid = threadIdx.x;
    const int wid = tid >> 5, lane = tid & 31;
    const int wm = wid >> 1, wn = wid & 1;
    const int bid = blockIdx.x;

    if (bid >= 136) {
        // ub[m] = <Am16h[m,:], b1> ; 8 warps x 16 rows
        const int r0 = (bid - 136) * 128 + wid * 16;
        for (int rr = 0; rr < 16; rr++) {
            const int m = r0 + rr;
            const __half* ph = g_Am16h + (size_t)m * N_;
            float s = 0.f;
            #pragma unroll 8
            for (int j = 0; j < 32; j++) {
                int n = j * 32 + lane;
                s += __half2float(ph[n]) * hb1[n];
            }
            #pragma unroll
            for (int o = 16; o > 0; o >>= 1) s += __shfl_xor_sync(0xFFFFFFFFu, s, o);
            if (lane == 0) g_u[m] = s;
        }
        return;
    }

    const bool isP = (bid < 128);
    const void *A, *B;
    int K, NKp, kc0, arow0, brow0;
    float* sBias = (float*)(smem + 512);
    if (isP) {
        int px = bid & 7, py = (bid >> 3) & 7, pz = bid >> 6;
        A = g_W116; B = g_Am16h;
        K = 1024; NKp = 8; kc0 = pz * 8;
        arow0 = py * 128; brow0 = px * 128;
    } else {
        int gx = bid - 128;
        A = g_hidh; B = g_G2h;
        K = 512; NKp = 8; kc0 = 0;
        arow0 = 0; brow0 = gx * 128;
        if (tid < 128) sBias[tid] = gb2[gx * 128 + tid];
    }

    const uint32_t T0 = sb + 1024;
    float acc[2][8][4];
    #pragma unroll
    for (int i = 0; i < 2; i++)
        #pragma unroll
        for (int j = 0; j < 8; j++)
            #pragma unroll
            for (int l = 0; l < 4; l++) acc[i][j][l] = 0.f;

    const int mi = lane >> 3, li = lane & 7;
    const int rowoff = (mi & 1) * 8 + li;
    const int coloff = (mi >> 1) * 16;

    ld_tile(T0, A, arow0, K, kc0, tid);
    ld_tile(T0 + TILE_B, B, brow0, K, kc0, tid);
    CP_COMMIT();

    for (int i = 0; i < NKp; i++) {
        const int cur = i & 1;
        if (i + 1 < NKp) {
            uint32_t nb = T0 + (cur ^ 1) * MEGA_SBUF;
            ld_tile(nb, A, arow0, K, kc0 + i + 1, tid);
            ld_tile(nb + TILE_B, B, brow0, K, kc0 + i + 1, tid);
            CP_COMMIT();
            asm volatile("cp.async.wait_group 1;" ::: "memory");
        } else {
            asm volatile("cp.async.wait_group 0;" ::: "memory");
        }
        __syncthreads();

        const uint32_t Ah = T0 + cur * MEGA_SBUF;
        const uint32_t Bh = Ah + TILE_B;

        #pragma unroll
        for (int ks = 0; ks < 4; ks++) {
            const int kb = ks * 32;
            uint32_t ahi[2][4];
            #pragma unroll
            for (int mt = 0; mt < 2; mt++) {
                uint32_t ra = swz((uint32_t)(wm * 32 + mt * 16 + rowoff) * 128 + kb + coloff);
                ldsm4(ahi[mt], Ah + ra);
            }
            #pragma unroll
            for (int g = 0; g < 4; g++) {
                uint32_t rb = swz((uint32_t)(wn * 64 + g * 16 + rowoff) * 128 + kb + coloff);
                uint32_t bh[4];
                ldsm4(bh, Bh + rb);
                #pragma unroll
                for (int mt = 0; mt < 2; mt++) {
                    #pragma unroll
                    for (int sub = 0; sub < 2; sub++) {
                        float* c = acc[mt][g * 2 + sub];
                        if (isP) mma_fp(c, ahi[mt], bh[sub], bh[2 + sub]);
                        else     mma_bf(c, ahi[mt], bh[sub], bh[2 + sub]);
                    }
                }
            }
        }
        __syncthreads();
    }

    if (isP) {
        const int pz = bid >> 6;
        float* Cf = g_zb + (size_t)pz * N_ * H_;
        #pragma unroll
        for (int mt = 0; mt < 2; mt++) {
            #pragma unroll
            for (int nt = 0; nt < 8; nt++) {
                const int rl = wm * 32 + mt * 16 + (lane >> 2);
                const int cl = wn * 64 + nt * 8 + (lane & 3) * 2;
                const int r0 = arow0 + rl;
                const int cg = brow0 + cl;
                *(float2*)(Cf + (size_t)r0 * N_ + cg)       = make_float2(acc[mt][nt][0], acc[mt][nt][1]);
                *(float2*)(Cf + (size_t)(r0 + 8) * N_ + cg) = make_float2(acc[mt][nt][2], acc[mt][nt][3]);
            }
        }
    } else {
        // sigmoid + column-mean over rows 0..63 -> gmean (tile buffers reusable after loop)
        float* gb = (float*)(smem + 1024);
        #pragma unroll
        for (int mt = 0; mt < 2; mt++) {
            #pragma unroll
            for (int nt = 0; nt < 8; nt++) {
                const int rl = wm * 32 + mt * 16 + (lane >> 2);
                const int cl = wn * 64 + nt * 8 + (lane & 3) * 2;
                float bb0 = sBias[cl], bb1 = sBias[cl + 1];
                gb[rl * 128 + cl]           = 1.0f / (1.0f + expf(-(acc[mt][nt][0] + bb0)));
                gb[rl * 128 + cl + 1]       = 1.0f / (1.0f + expf(-(acc[mt][nt][1] + bb1)));
                gb[(rl + 8) * 128 + cl]     = 1.0f / (1.0f + expf(-(acc[mt][nt][2] + bb0)));
                gb[(rl + 8) * 128 + cl + 1] = 1.0f / (1.0f + expf(-(acc[mt][nt][3] + bb1)));
            }
        }
        __syncthreads();
        if (tid < 128) {
            float s = 0.f;
            #pragma unroll 8
            for (int r = 0; r < 64; r++) s += gb[r * 128 + tid];
            g_gmean[brow0 + tid] = s * (1.0f / 64.0f);
        }
    }
}

// ---------------- k_mega3: M GEMM 2-pass (128 CTAs) + bias_c (8) ----------------
__global__ __launch_bounds__(256, 1) void k_mega3(const float* __restrict__ nb2) {
    extern __shared__ __align__(1024) char smem[];
    uint32_t sb = smem_u32(smem);
    const int tid = threadIdx.x;
    const int wid = tid >> 5, lane = tid & 31;
    const int wm = wid >> 1, wn = wid & 1;
    const int bid = blockIdx.x;

    if (bid >= 128) {
        const int r0 = (bid - 128) * 128 + wid * 16;
        for (int rr = 0; rr < 16; rr++) {
            const int h = r0 + rr;
            const __half* pw = g_W2t16 + (size_t)h * N_;
            float s = 0.f;
            #pragma unroll 8
            for (int j = 0; j < 32; j++) {
                int m = j * 32 + lane;
                s += g_gmean[m] * g_u[m] * __half2float(pw[m]);
            }
            #pragma unroll
            for (int o = 16; o > 0; o >>= 1) s += __shfl_xor_sync(0xFFFFFFFFu, s, o);
            if (lane == 0) g_cvec[h] = s + nb2[h];
        }
        return;
    }

    const int mx = bid & 7, my = (bid >> 3) & 7, mz = bid >> 6;
    const int arow0 = my * 128, brow0 = mx * 128;
    const int kc0 = mz * 8;

    const uint32_t T0 = sb + 1024;
    float acc[2][8][4];
    #pragma unroll
    for (int i = 0; i < 2; i++)
        #pragma unroll
        for (int j = 0; j < 8; j++)
            #pragma unroll
            for (int l = 0; l < 4; l++) acc[i][j][l] = 0.f;

    const int mi = lane >> 3, li = lane & 7;
    const int rowoff = (mi & 1) * 8 + li;
    const int coloff = (mi >> 1) * 16;

    ld_tile(T0, g_W2t16, arow0, 1024, kc0, tid);
    ld_tile(T0 + 2 * TILE_B, g_P16h, brow0, 1024, kc0, tid);
    ld_tile(T0 + 3 * TILE_B, g_P16l, brow0, 1024, kc0, tid);
    CP_COMMIT();

    for (int i = 0; i < 8; i++) {
        const int cur = i & 1;
        if (i + 1 < 8) {
            uint32_t nb = T0 + (cur ^ 1) * BUF_B;
            ld_tile(nb, g_W2t16, arow0, 1024, kc0 + i + 1, tid);
            ld_tile(nb + 2 * TILE_B, g_P16h, brow0, 1024, kc0 + i + 1, tid);
            ld_tile(nb + 3 * TILE_B, g_P16l, brow0, 1024, kc0 + i + 1, tid);
            CP_COMMIT();
            asm volatile("cp.async.wait_group 1;" ::: "memory");
        } else {
            asm volatile("cp.async.wait_group 0;" ::: "memory");
        }
        __syncthreads();

        const uint32_t Ah = T0 + cur * BUF_B;
        const uint32_t Bh = Ah + 2 * TILE_B;
        const uint32_t Bl = Ah + 3 * TILE_B;

        #pragma unroll
        for (int ks = 0; ks < 4; ks++) {
            const int kb = ks * 32;
            uint32_t ahi[2][4];
            #pragma unroll
            for (int mt = 0; mt < 2; mt++) {
                uint32_t ra = swz((uint32_t)(wm * 32 + mt * 16 + rowoff) * 128 + kb + coloff);
                ldsm4(ahi[mt], Ah + ra);
            }
            #pragma unroll
            for (int g = 0; g < 4; g++) {
                uint32_t rb = swz((uint32_t)(wn * 64 + g * 16 + rowoff) * 128 + kb + coloff);
                uint32_t bh[4], bl[4];
                ldsm4(bh, Bh + rb);
                ldsm4(bl, Bl + rb);
                #pragma unroll
                for (int mt = 0; mt < 2; mt++) {
                    #pragma unroll
                    for (int sub = 0; sub < 2; sub++) {
                        float* c = acc[mt][g * 2 + sub];
                        mma_fp(c, ahi[mt], bh[sub], bh[2 + sub]);
                        mma_fp(c, ahi[mt], bl[sub], bl[2 + sub]);
                    }
                }
            }
        }
        __syncthreads();
    }

    float* Cf = g_zb + (size_t)mz * N_ * H_;
    #pragma unroll
    for (int mt = 0; mt < 2; mt++) {
        #pragma unroll
        for (int nt = 0; nt < 8; nt++) {
            const int rl = wm * 32 + mt * 16 + (lane >> 2);
            const int cl = wn * 64 + nt * 8 + (lane & 3) * 2;
            const int r0 = arow0 + rl;
            const int cg = brow0 + cl;
            *(float2*)(Cf + (size_t)r0 * H_ + cg)       = make_float2(acc[mt][nt][0], acc[mt][nt][1]);
            *(float2*)(Cf + (size_t)(r0 + 8) * H_ + cg) = make_float2(acc[mt][nt][2], acc[mt][nt][3]);
        }
    }
}

// ---------------- fp16 single-pass GEMM + fused residual/LayerNorm epilogue (unchanged) ----------------
#define FTILE_B 16384
#define FSTAGE_B (2 * FTILE_B)
#define FGEMM_SMEM (1024 + 3 * FSTAGE_B)

__global__ __launch_bounds__(256, 2) void fgemm(
    const __half* __restrict__ A,
    const __half* __restrict__ Bh,
    const float* __restrict__ bias,
    __half* __restrict__ Ch,
    const float* __restrict__ lw, const float* __restrict__ lb,
    float* __restrict__ out, int M, int Nn, int K)
{
    extern __shared__ __align__(1024) char smem[];
    uint32_t sb = smem_u32(smem);
    const int tid = threadIdx.x;
    const int wid = tid >> 5, lane = tid & 31;
    const int wm = wid >> 1, wn = wid & 1;
    const int bx = blockIdx.x, by = blockIdx.y;

    float* sBias = (float*)(smem + 512);
    if (tid < 128) sBias[tid] = bias[bx * 128 + tid];

    const uint32_t T0 = sb + 1024;
    const int NK = K >> 6;
    const int arow0 = by * 128, brow0 = bx * 128;

    float acc[2][8][4];
    #pragma unroll
    for (int i = 0; i < 2; i++)
        #pragma unroll
        for (int j = 0; j < 8; j++)
            #pragma unroll
            for (int l = 0; l < 4; l++) acc[i][j][l] = 0.f;

    const int mi = lane >> 3, li = lane & 7;
    const int rowoff = (mi & 1) * 8 + li;
    const int coloff = (mi >> 1) * 16;

    #pragma unroll
    for (int s = 0; s < 2; s++) {
        uint32_t st = T0 + s * FSTAGE_B;
        ld_tile(st,           A,  arow0, K, s, tid);
        ld_tile(st + FTILE_B, Bh, brow0, K, s, tid);
        CP_COMMIT();
    }

    for (int kc = 0; kc < NK; kc++) {
        if (kc == NK - 1) asm volatile("cp.async.wait_group 0;" ::: "memory");
        else              asm volatile("cp.async.wait_group 1;" ::: "memory");
        __syncthreads();

        if (kc + 2 < NK) {
            uint32_t st = T0 + ((kc + 2) % 3) * FSTAGE_B;
            ld_tile(st,           A,  arow0, K, kc + 2, tid);
            ld_tile(st + FTILE_B, Bh, brow0, K, kc + 2, tid);
            CP_COMMIT();
        }

        const uint32_t Sa = T0 + (kc % 3) * FSTAGE_B;
        const uint32_t Sh = Sa + FTILE_B;

        #pragma unroll
        for (int ks = 0; ks < 4; ks++) {
            const int kb = ks * 32;
            uint32_t a[2][4];
            #pragma unroll
            for (int mt = 0; mt < 2; mt++) {
                uint32_t ra = swz((uint32_t)(wm * 32 + mt * 16 + rowoff) * 128 + kb + coloff);
                ldsm4(a[mt], Sa + ra);
            }
            #pragma unroll
            for (int g = 0; g < 4; g++) {
                uint32_t rb = swz((uint32_t)(wn * 64 + g * 16 + rowoff) * 128 + kb + coloff);
                uint32_t bh[4];
                ldsm4(bh, Sh + rb);
                #pragma unroll
                for (int mt = 0; mt < 2; mt++) {
                    #pragma unroll
                    for (int sub = 0; sub < 2; sub++) {
                        mma_fp(acc[mt][g * 2 + sub], a[mt], bh[sub], bh[2 + sub]);
                    }
                }
            }
        }
    }

    #pragma unroll
    for (int mt = 0; mt < 2; mt++) {
        #pragma unroll
        for (int nt = 0; nt < 8; nt++) {
            const int r0 = by * 128 + wm * 32 + mt * 16 + (lane >> 2);
            const int cb = wn * 64 + nt * 8 + (lane & 3) * 2;
            const int cg = bx * 128 + cb;
            float bb0 = sBias[cb], bb1 = sBias[cb + 1];
            __half h0 = __float2half(acc[mt][nt][0] + bb0);
            __half h1 = __float2half(acc[mt][nt][1] + bb1);
            __half h2 = __float2half(acc[mt][nt][2] + bb0);
            __half h3 = __float2half(acc[mt][nt][3] + bb1);
            *(uint32_t*)(Ch + (size_t)r0 * Nn + cg)       = ((uint32_t)hfbits(h1) << 16) | hfbits(h0);
            *(uint32_t*)(Ch + (size_t)(r0 + 8) * Nn + cg) = ((uint32_t)hfbits(h3) << 16) | hfbits(h2);
        }
    }

    __shared__ unsigned int sflag;
    __threadfence();
    __syncthreads();
    if (tid == 0) sflag = atomicAdd(&g_cnt[by], 1u);
    __syncthreads();
    if (sflag != 7) return;
    __threadfence();

    const float gw = 1.0f + tanhf(1.0f / 1024.0f);
    for (int r16 = 0; r16 < 16; r16++) {
        const size_t row = (size_t)by * 128 + wid * 16 + r16;
        const __half* ph = g_hA16 + row * H_;
        const __half* pm = Ch + row * H_;
        float v[32];
        float s = 0.f;
        #pragma unroll
        for (int j = 0; j < 8; j++) {
            int c = (j * 32 + lane) * 4;
            uint2 ha = *(const uint2*)(ph + c);
            uint2 ma = *(const uint2*)(pm + c);
            __half2 h01 = *reinterpret_cast<__half2*>(&ha.x);
            __half2 h23 = *reinterpret_cast<__half2*>(&ha.y);
            __half2 m01 = *reinterpret_cast<__half2*>(&ma.x);
            __half2 m23 = *reinterpret_cast<__half2*>(&ma.y);
            v[j * 4 + 0] = __low2float(h01) * gw + __low2float(m01);
            v[j * 4 + 1] = __high2float(h01) * gw + __high2float(m01);
            v[j * 4 + 2] = __low2float(h23) * gw + __low2float(m23);
            v[j * 4 + 3] = __high2float(h23) * gw + __high2float(m23);
            s += v[j * 4 + 0] + v[j * 4 + 1] + v[j * 4 + 2] + v[j * 4 + 3];
        }
        #pragma unroll
        for (int o = 16; o > 0; o >>= 1) s += __shfl_xor_sync(0xFFFFFFFFu, s, o);
        const float mu = s * (1.0f / H_);
        float ss = 0.f;
        #pragma unroll
        for (int j = 0; j < 32; j++) {
            v[j] -= mu;
            ss += v[j] * v[j];
        }
        #pragma unroll
        for (int o = 16; o > 0; o >>= 1) ss += __shfl_xor_sync(0xFFFFFFFFu, ss, o);
        const float rstd = rsqrtf(ss * (1.0f / H_) + 1e-5f);
        float* po = out + row * H_;
        #pragma unroll
        for (int j = 0; j < 8; j++) {
            int c = (j * 32 + lane) * 4;
            float4 w4 = *(const float4*)(lw + c);
            float4 b4 = *(const float4*)(lb + c);
            float4 o4;
            o4.x = v[j * 4 + 0] * rstd * w4.x + b4.x;
            o4.y = v[j * 4 + 1] * rstd * w4.y + b4.y;
            o4.z = v[j * 4 + 2] * rstd * w4.z + b4.z;
            o4.w = v[j * 4 + 3] * rstd * w4.w + b4.w;
            *(float4*)(po + c) = o4;
        }
    }
}

// ---------------- small kernels ----------------
__global__ __launch_bounds__(256) void k_preW(const float* __restrict__ h,
                                              const float* __restrict__ h2n_W,
                                              const float* __restrict__ n2h_W,
                                              const float* __restrict__ gate_W1,
                                              const float* __restrict__ gate_W2) {
    const int bid = blockIdx.x;
    const int tx = threadIdx.x & 31, ty = threadIdx.x >> 5;
    __shared__ float tt[32][33];
    if (bid < 512) {
        int b = bid >> 2;
        int hh = (bid & 3) * 256 + threadIdx.x;
        if (b >= 64) { g_hgHi[b * H_ + hh] = __float2bfloat16(0.f); return; }
        const float* p = h + (size_t)b * T_ * H_ + hh;
        __half* q = g_hA16 + (size_t)b * T_ * H_ + hh;
        float s = 0.f;
        #pragma unroll 4
        for (int t = 0; t < T_; t++) {
            float v = p[(size_t)t * H_];
            q[(size_t)t * H_] = __float2half(v);
            s += v;
        }
        float mean = s * (1.0f / T_);
        g_hgate[b * H_ + hh] = mean;
        g_hgHi[b * H_ + hh] = __float2bfloat16(mean);
        return;
    }
    const int wb = bid - 512;
    if (wb < 1024) {
        int i = wb * 256 + threadIdx.x;
        float4 v = ((const float4*)h2n_W)[i];
        __half h0 = __float2half(v.x), h1 = __float2half(v.y);
        __half h2 = __float2half(v.z), h3 = __float2half(v.w);
        uint2 hv;
        hv.x = ((uint32_t)hfbits(h1) << 16) | hfbits(h0);
        hv.y = ((uint32_t)hfbits(h3) << 16) | hfbits(h2);
        ((uint2*)g_W116)[i] = hv;
        return;
    }
    const float* W; int Rin, Cin, bx, by;
    if (wb < 2048) { W = n2h_W;   Rin = N_;   Cin = H_;   int l = wb - 1024; bx = l & 31; by = l >> 5; }
    else if (wb < 2560) { W = gate_W1; Rin = H_; Cin = HID_; int l = wb - 2048; bx = l & 15; by = l >> 4; }
    else { W = gate_W2; Rin = HID_; Cin = N_;  int l = wb - 2560; bx = l & 31; by = l >> 5; }
    int c0 = bx * 32, r0 = by * 32;
    #pragma unroll
    for (int i = 0; i < 4; i++)
        tt[ty + i * 8][tx] = W[(size_t)(r0 + ty + i * 8) * Cin + c0 + tx];
    __syncthreads();
    #pragma unroll
    for (int i = 0; i < 4; i++) {
        int oc = ty + i * 8;
        size_t o = (size_t)(c0 + oc) * Rin + r0 + tx;
        float v = tt[tx][oc];
        if (wb < 2048)      g_W2t16[o] = __float2half(v);
        else if (wb < 2560) g_G1h[o]   = __float2bfloat16(v);
        else                g_G2h[o]   = __float2bfloat16(v);
    }
}

__global__ void k_meanB() {
    int hh = blockIdx.x * blockDim.x + threadIdx.x;
    if (hh >= H_) return;
    if (hh < 128) g_cnt[hh] = 0u;
    float s = 0.f;
    #pragma unroll
    for (int b = 0; b < B_; b++) s += g_hgate[b * H_ + hh];
    g_hmean[hh] = s * (1.0f / B_);
}

__global__ __launch_bounds__(256) void k_enorm(const float* __restrict__ E_dyn) {
    int i = blockIdx.x;
    __shared__ float red[256];
    float vals[4];
    float ss = 0.f;
    #pragma unroll
    for (int j = 0; j < 4; j++) {
        int hh = threadIdx.x + j * 256;
        float v = E_dyn[i * H_ + hh] + g_hmean[hh];
        vals[j] = v; ss += v * v;
    }
    red[threadIdx.x] = ss; __syncthreads();
    for (int off = 128; off > 0; off >>= 1) {
        if (threadIdx.x < off) red[threadIdx.x] += red[threadIdx.x + off];
        __syncthreads();
    }
    float inv = 1.0f / fmaxf(sqrtf(red[0]), 1e-12f);
    #pragma unroll
    for (int j = 0; j < 4; j++) {
        int hh = threadIdx.x + j * 256;
        g_Ehi[i * H_ + hh] = __float2bfloat16(vals[j] * inv);
    }
}

// combS (36 CTAs, 4 partials) + combG (32 CTAs)
__global__ __launch_bounds__(256) void k_combSG(const float* __restrict__ b1) {
    if (blockIdx.x >= 36) {
        const int base = (blockIdx.x - 36) * 2048;
        const float* z = g_zb + ZBG_OFF;
        #pragma unroll
        for (int k = 0; k < 8; k++) {
            int i = base + k * 256 + threadIdx.x;
            int n = i & (HID_ - 1);
            float v = z[i] + z[65536 + i] + z[2*65536 + i] + z[3*65536 + i] + b1[n];
            v = 0.5f * v * (1.0f + erff(v * 0.70710678118654752f));
            g_hidh[i] = __float2bfloat16(v);
        }
        return;
    }
    int t = blockIdx.x, i = 0;
    while (t >= 8 - i) { t -= 8 - i; i++; }
    const int by = i, bx = i + t;
    const float* z0 = g_zb + (size_t)blockIdx.x * 16384;
    const float* z1 = g_zb + (size_t)(36 + blockIdx.x) * 16384;
    const float* z2 = g_zb + (size_t)(72 + blockIdx.x) * 16384;
    const float* z3 = g_zb + (size_t)(108 + blockIdx.x) * 16384;
    __shared__ float sT[128][65];
    const int tid = threadIdx.x;
    #pragma unroll
    for (int half = 0; half < 2; half++) {
        const int r0 = half * 64;
        #pragma unroll 4
        for (int it = 0; it < 32; it++) {
            int idx = it * 256 + tid;
            int r = idx >> 7, c = idx & 127;
            int o = (r0 + r) * 128 + c;
            float v = fmaxf((z0[o] + z1[o]) + (z2[o] + z3[o]), 0.f);
            g_S[(size_t)(by * 128 + r0 + r) * N_ + bx * 128 + c] = v;
            sT[c][r] = v;
        }
        if (bx != by) {
            __syncthreads();
            #pragma unroll 4
            for (int it = 0; it < 32; it++) {
                int idx = it * 256 + tid;
                int c = idx >> 6, rr = idx & 63;
                g_S[(size_t)(bx * 128 + c) * N_ + by * 128 + r0 + rr] = sT[c][rr];
            }
            __syncthreads();
        }
    }
}

__global__ __launch_bounds__(256) void k_rowsum() {
    int i = blockIdx.x;
    __shared__ float red[256];
    float s = 0.f;
    for (int j = threadIdx.x; j < N_; j += 256) s += g_S[i * N_ + j];
    red[threadIdx.x] = s; __syncthreads();
    for (int off = 128; off > 0; off >>= 1) {
        if (threadIdx.x < off) red[threadIdx.x] += red[threadIdx.x + off];
        __syncthreads();
    }
    if (threadIdx.x == 0) g_rowsum[i] = 1.0f / (red[0] + 1e-6f);
}

// Abase elementwise (S symmetric, NO gmean): v = a*Ap + (1-a)*0.5*S*(ir[m]+ir[n]) -> fp16 single
__global__ void k_amix(const float* __restrict__ Ap, const float* __restrict__ alpha_raw) {
    int idx = blockIdx.x * blockDim.x + threadIdx.x;
    if (idx >= N_*N_) return;
    int m = idx >> 10, n = idx & 1023;
    float alpha = 1.0f / (1.0f + expf(-alpha_raw[0]));
    float v = alpha * Ap[idx] + (1.0f - alpha) * 0.5f * g_S[idx] * (g_rowsum[m] + g_rowsum[n]);
    g_Am16h[idx] = __float2half(v);
}

// combine 2 split-K partials, apply gmean[m] -> fp16 hi/lo (P)
__global__ void k_combP() {
    int i = blockIdx.x * blockDim.x + threadIdx.x;
    if (i >= N_*H_) return;
    float v = (g_zb[i] + g_zb[(size_t)N_*H_ + i]) * g_gmean[i & 1023];
    __half h = __float2half(v);
    g_P16h[i] = h;
    g_P16l[i] = __float2half(v - __half2float(h));
}

// combine 2 split-K partials -> fp16 (Mcomb)
__global__ void k_combM() {
    int i = blockIdx.x * blockDim.x + threadIdx.x;
    if (i >= H_*H_) return;
    g_M16h[i] = __float2half(g_zb[i] + g_zb[(size_t)N_*H_ + i]);
}

// ---------------- launcher ----------------
extern "C" void kernel_launch(void* const* d_in, const int* in_sizes, int n_in,
                              void* d_out, int out_size) {
    const float* h_time    = (const float*)d_in[0];
    const float* A_pearson = (const float*)d_in[1];
    const float* E_dyn     = (const float*)d_in[2];
    const float* alpha_raw = (const float*)d_in[3];
    // d_in[4] = tau_raw : analytically eliminated (mean over softmax axis == 1/N)
    const float* gate_W1   = (const float*)d_in[5];
    const float* gate_b1   = (const float*)d_in[6];
    const float* gate_W2   = (const float*)d_in[7];
    const float* gate_b2   = (const float*)d_in[8];
    const float* h2n_W     = (const float*)d_in[9];
    const float* h2n_b     = (const float*)d_in[10];
    const float* n2h_W     = (const float*)d_in[11];
    const float* n2h_b     = (const float*)d_in[12];
    const float* ln_w      = (const float*)d_in[13];
    const float* ln_b      = (const float*)d_in[14];
    float* out = (float*)d_out;

    __half *p_hA16, *p_M16h, *p_msg16;
    float *p_cvec;
    cudaGetSymbolAddress((void**)&p_hA16, g_hA16);
    cudaGetSymbolAddress((void**)&p_M16h, g_M16h);
    cudaGetSymbolAddress((void**)&p_msg16, g_msg16);
    cudaGetSymbolAddress((void**)&p_cvec, g_cvec);

    cudaFuncSetAttribute(k_mega,  cudaFuncAttributeMaxDynamicSharedMemorySize, MEGA_SMEM);
    cudaFuncSetAttribute(k_mega2, cudaFuncAttributeMaxDynamicSharedMemorySize, MEGA_SMEM);
    cudaFuncSetAttribute(k_mega3, cudaFuncAttributeMaxDynamicSharedMemorySize, GEMM_SMEM);
    cudaFuncSetAttribute(fgemm,   cudaFuncAttributeMaxDynamicSharedMemorySize, FGEMM_SMEM);

    // 0: h_time pre (fp16 + h_gate) + all weight conversions
    k_preW<<<3584, 256>>>(h_time, h2n_W, n2h_W, gate_W1, gate_W2);
    // 1: batch-mean (+ LN counter reset)
    k_meanB<<<(H_ + 255) / 256, 256>>>();
    // 2: E row-normalize
    k_enorm<<<N_, 256>>>(E_dyn);
    // 3: S (36 tiles, split-K4) ∥ gate1 (split-K4), 2 CTAs/SM
    k_mega<<<dim3(52, 1, 4), 256, MEGA_SMEM>>>();
    // 4: combS (4 partials + mirror) ∥ combG (+gelu)
    k_combSG<<<68, 256>>>(gate_b1);
    // 5: row sums -> reciprocals
    k_rowsum<<<N_, 256>>>();
    // 6: Abase -> fp16 (gmean deferred, single)
    k_amix<<<(N_*N_ + 255) / 256, 256>>>(A_pearson, alpha_raw);
    // 7: P GEMM single-pass (split-K2) ∥ gate2 ∥ ub
    k_mega2<<<144, 256, MEGA_SMEM>>>(gate_b2, h2n_b);
    // 8: combine P partials * gmean -> fp16 split
    k_combP<<<(N_*H_ + 255) / 256, 256>>>();
    // 9: M GEMM 2-pass (split-K2) ∥ bias_c (cvec)
    k_mega3<<<136, 256, GEMM_SMEM>>>(n2h_b);
    // 10: combine M partials -> fp16
    k_combM<<<(H_*H_ + 255) / 256, 256>>>();
    // 11: THE big GEMM + fused residual/LayerNorm epilogue
    fgemm<<<dim3(H_ / 128, BT_ / 128), 256, FGEMM_SMEM>>>(
        p_hA16, p_M16h, p_cvec, p_msg16, ln_w, ln_b, out, BT_, H_, H_);
}

// round 15
// speedup vs baseline: 1.0131x; 1.0131x over previous
#include <cuda_runtime.h>
#include <cuda_bf16.h>
#include <cuda_fp16.h>
#include <math.h>
#include <stdint.h>

#define N_ 1024
#define H_ 1024
#define B_ 64
#define T_ 256
#define BT_ (B_*T_)
#define HID_ 512

typedef __nv_bfloat16 bf16;

// ---------------- scratch (static device globals; no allocation) ----------------
__device__ __half g_hA16[BT_*H_];                  // h_time fp16
__device__ float g_hgate[B_*H_];
__device__ bf16  g_hgHi[128*H_];                   // h_gate bf16, padded to 128 rows
__device__ float g_hmean[H_];
__device__ bf16  g_Ehi[N_*H_];
__device__ float g_S[N_*N_];
__device__ float g_rowsum[N_];                     // stores 1/(rowsum+1e-6)
__device__ bf16  g_G1h[HID_*H_];                   // gate_W1^T bf16
__device__ bf16  g_G2h[N_*HID_];                   // gate_W2^T bf16
__device__ bf16  g_hidh[128*HID_];
__device__ float g_gmean[N_];
__device__ __half g_Am16h[N_*N_], g_Am16l[N_*N_];  // A_base fp16 hi/lo (gmean deferred)
__device__ __half g_W116[H_*N_];                   // h2n_W fp16
__device__ __half g_W2t16[H_*N_];                  // n2h_W^T fp16
__device__ __half g_P16h[H_*N_], g_P16l[H_*N_];    // P fp16 hi/lo (gmean applied)
__device__ __half g_M16h[H_*H_];                   // McombT fp16
__device__ float g_zb[2*(size_t)N_*H_];            // partials: S tiles [0,72*16384) ; gate1 at ZBG_OFF; P/M slabs
__device__ float g_u[N_];                          // ub[m] = <Abase[m],b1> (no gmean)
__device__ float g_cvec[H_];
__device__ __half g_msg16[BT_*H_];
__device__ unsigned int g_cnt[128];                // fgemm row-block completion counters

#define ZBG_OFF (72 * 16384)                       // gate1 partial region (4 x 65536 floats)

// ---------------- helpers ----------------
__device__ __forceinline__ unsigned short hfbits(__half x) {
    return *reinterpret_cast<unsigned short*>(&x);
}
__device__ __forceinline__ uint32_t smem_u32(const void* p) {
    uint32_t a;
    asm("{ .reg .u64 t; cvta.to.shared.u64 t, %1; cvt.u32.u64 %0, t; }" : "=r"(a) : "l"(p));
    return a;
}
__device__ __forceinline__ uint32_t swz(uint32_t off) {
    return off ^ ((off >> 3) & 0x70);
}
#define CP_COMMIT() asm volatile("cp.async.commit_group;" ::: "memory")

__device__ __forceinline__ void ldsm4(uint32_t (&r)[4], uint32_t addr) {
    asm volatile("ldmatrix.sync.aligned.m8n8.x4.shared.b16 {%0,%1,%2,%3}, [%4];"
        : "=r"(r[0]), "=r"(r[1]), "=r"(r[2]), "=r"(r[3]) : "r"(addr));
}
__device__ __forceinline__ void mma_bf(float* c, const uint32_t* a, uint32_t b0, uint32_t b1) {
    asm volatile("mma.sync.aligned.m16n8k16.row.col.f32.bf16.bf16.f32 "
        "{%0,%1,%2,%3}, {%4,%5,%6,%7}, {%8,%9}, {%0,%1,%2,%3};"
        : "+f"(c[0]), "+f"(c[1]), "+f"(c[2]), "+f"(c[3])
        : "r"(a[0]), "r"(a[1]), "r"(a[2]), "r"(a[3]), "r"(b0), "r"(b1));
}
__device__ __forceinline__ void mma_fp(float* c, const uint32_t* a, uint32_t b0, uint32_t b1) {
    asm volatile("mma.sync.aligned.m16n8k16.row.col.f32.f16.f16.f32 "
        "{%0,%1,%2,%3}, {%4,%5,%6,%7}, {%8,%9}, {%0,%1,%2,%3};"
        : "+f"(c[0]), "+f"(c[1]), "+f"(c[2]), "+f"(c[3])
        : "r"(a[0]), "r"(a[1]), "r"(a[2]), "r"(a[3]), "r"(b0), "r"(b1));
}

// load one 128row x 64col 16-bit tile (SW128 swizzled, 128B/row); 256 threads
__device__ __forceinline__ void ld_tile(uint32_t sdst, const void* __restrict__ g,
                                        int row0, int K, int kc, int tid) {
    const int row = tid >> 1, half = tid & 1;
    const char* src = (const char*)g + (((size_t)(row0 + row) * K + (kc << 6)) << 1) + half * 64;
    uint32_t rb = (uint32_t)row * 128 + (uint32_t)half * 64;
    #pragma unroll
    for (int j = 0; j < 4; j++) {
        uint32_t sw = swz(rb + (j << 4));
        asm volatile("cp.async.cg.shared.global [%0], [%1], 16;"
            :: "r"(sdst + sw), "l"(src + (j << 4)));
    }
}

#define TILE_B 16384
#define BUF_B  65536
#define GEMM_SMEM (1024 + 2 * BUF_B)

// ---------------- k_mega: fused S (36 tiles x split-K2) + gate1 (4 tiles x split-K4) ----------------
// grid (52, 1, 2). bx<36: S tile; bx>=36 && bz==0: gate1 subtile.
__global__ __launch_bounds__(256, 1) void k_mega() {
    extern __shared__ __align__(1024) char smem[];
    uint32_t sb = smem_u32(smem);
    const int tid = threadIdx.x;
    const int wid = tid >> 5, lane = tid & 31;
    const int wm = wid >> 1, wn = wid & 1;

    const void *A, *B;
    int arow0, brow0, NKp, kc0, ostride, ocol0;
    float* dst;
    if (blockIdx.x < 36) {
        int t = blockIdx.x, i = 0;
        while (t >= 8 - i) { t -= 8 - i; i++; }
        A = g_Ehi; B = g_Ehi;
        arow0 = i * 128; brow0 = (i + t) * 128;
        NKp = 8; kc0 = blockIdx.z * 8;
        dst = g_zb + ((size_t)blockIdx.z * 36 + blockIdx.x) * 16384;
        ostride = 128; ocol0 = 0;
    } else {
        if (blockIdx.z) return;
        int idx = blockIdx.x - 36, gx = idx & 3, gz = idx >> 2;
        A = g_hgHi; B = g_G1h;
        arow0 = 0; brow0 = gx * 128;
        NKp = 4; kc0 = gz * 4;
        dst = g_zb + ZBG_OFF + (size_t)gz * 65536;
        ostride = 512; ocol0 = gx * 128;
    }

    const uint32_t T0 = sb + 1024;
    float acc[2][8][4];
    #pragma unroll
    for (int i = 0; i < 2; i++)
        #pragma unroll
        for (int j = 0; j < 8; j++)
            #pragma unroll
            for (int l = 0; l < 4; l++) acc[i][j][l] = 0.f;

    const int mi = lane >> 3, li = lane & 7;
    const int rowoff = (mi & 1) * 8 + li;
    const int coloff = (mi >> 1) * 16;

    ld_tile(T0, A, arow0, 1024, kc0, tid);
    ld_tile(T0 + 2 * TILE_B, B, brow0, 1024, kc0, tid);
    CP_COMMIT();

    for (int i = 0; i < NKp; i++) {
        const int cur = i & 1;
        if (i + 1 < NKp) {
            uint32_t nb = T0 + (cur ^ 1) * BUF_B;
            ld_tile(nb, A, arow0, 1024, kc0 + i + 1, tid);
            ld_tile(nb + 2 * TILE_B, B, brow0, 1024, kc0 + i + 1, tid);
            CP_COMMIT();
            asm volatile("cp.async.wait_group 1;" ::: "memory");
        } else {
            asm volatile("cp.async.wait_group 0;" ::: "memory");
        }
        __syncthreads();

        const uint32_t Ah = T0 + cur * BUF_B;
        const uint32_t Bh = Ah + 2 * TILE_B;

        #pragma unroll
        for (int ks = 0; ks < 4; ks++) {
            const int kb = ks * 32;
            uint32_t ahi[2][4];
            #pragma unroll
            for (int mt = 0; mt < 2; mt++) {
                uint32_t ra = swz((uint32_t)(wm * 32 + mt * 16 + rowoff) * 128 + kb + coloff);
                ldsm4(ahi[mt], Ah + ra);
            }
            #pragma unroll
            for (int g = 0; g < 4; g++) {
                uint32_t rb = swz((uint32_t)(wn * 64 + g * 16 + rowoff) * 128 + kb + coloff);
                uint32_t bh[4];
                ldsm4(bh, Bh + rb);
                #pragma unroll
                for (int mt = 0; mt < 2; mt++) {
                    #pragma unroll
                    for (int sub = 0; sub < 2; sub++) {
                        mma_bf(acc[mt][g * 2 + sub], ahi[mt], bh[sub], bh[2 + sub]);
                    }
                }
            }
        }
        __syncthreads();
    }

    #pragma unroll
    for (int mt = 0; mt < 2; mt++) {
        #pragma unroll
        for (int nt = 0; nt < 8; nt++) {
            const int rl = wm * 32 + mt * 16 + (lane >> 2);
            const int cl = wn * 64 + nt * 8 + (lane & 3) * 2;
            *(float2*)(dst + rl * ostride + ocol0 + cl)       = make_float2(acc[mt][nt][0], acc[mt][nt][1]);
            *(float2*)(dst + (rl + 8) * ostride + ocol0 + cl) = make_float2(acc[mt][nt][2], acc[mt][nt][3]);
        }
    }
}

// ---------------- k_mega2: P GEMM (128 CTAs) + gate2 (8) + ub (8) ----------------
__global__ __launch_bounds__(256, 1) void k_mega2(const float* __restrict__ gb2,
                                                  const float* __restrict__ hb1) {
    extern __shared__ __align__(1024) char smem[];
    uint32_t sb = smem_u32(smem);
    const int tid = threadIdx.x;
    const int wid = tid >> 5, lane = tid & 31;
    const int wm = wid >> 1, wn = wid & 1;
    const int bid = blockIdx.x;

    if (bid >= 136) {
        // ub[m] = <(Am16h+Am16l)[m,:], b1> ; 8 warps x 16 rows
        const int r0 = (bid - 136) * 128 + wid * 16;
        for (int rr = 0; rr < 16; rr++) {
            const int m = r0 + rr;
            const __half* ph = g_Am16h + (size_t)m * N_;
            const __half* pl = g_Am16l + (size_t)m * N_;
            float s = 0.f;
            #pragma unroll 8
            for (int j = 0; j < 32; j++) {
                int n = j * 32 + lane;
                s += (__half2float(ph[n]) + __half2float(pl[n])) * hb1[n];
            }
            #pragma unroll
            for (int o = 16; o > 0; o >>= 1) s += __shfl_xor_sync(0xFFFFFFFFu, s, o);
            if (lane == 0) g_u[m] = s;
        }
        return;
    }

    const bool isP = (bid < 128);
    const void *A, *Bh_, *Bl_;
    int K, NKp, kc0, arow0, brow0;
    float* sBias = (float*)(smem + 512);
    if (isP) {
        int px = bid & 7, py = (bid >> 3) & 7, pz = bid >> 6;
        A = g_W116; Bh_ = g_Am16h; Bl_ = g_Am16l;
        K = 1024; NKp = 8; kc0 = pz * 8;
        arow0 = py * 128; brow0 = px * 128;
    } else {
        int gx = bid - 128;
        A = g_hidh; Bh_ = g_G2h; Bl_ = nullptr;
        K = 512; NKp = 8; kc0 = 0;
        arow0 = 0; brow0 = gx * 128;
        if (tid < 128) sBias[tid] = gb2[gx * 128 + tid];
    }

    const uint32_t T0 = sb + 1024;
    float acc[2][8][4];
    #pragma unroll
    for (int i = 0; i < 2; i++)
        #pragma unroll
        for (int j = 0; j < 8; j++)
            #pragma unroll
            for (int l = 0; l < 4; l++) acc[i][j][l] = 0.f;

    const int mi = lane >> 3, li = lane & 7;
    const int rowoff = (mi & 1) * 8 + li;
    const int coloff = (mi >> 1) * 16;

    ld_tile(T0, A, arow0, K, kc0, tid);
    ld_tile(T0 + 2 * TILE_B, Bh_, brow0, K, kc0, tid);
    if (isP) ld_tile(T0 + 3 * TILE_B, Bl_, brow0, K, kc0, tid);
    CP_COMMIT();

    for (int i = 0; i < NKp; i++) {
        const int cur = i & 1;
        if (i + 1 < NKp) {
            uint32_t nb = T0 + (cur ^ 1) * BUF_B;
            ld_tile(nb, A, arow0, K, kc0 + i + 1, tid);
            ld_tile(nb + 2 * TILE_B, Bh_, brow0, K, kc0 + i + 1, tid);
            if (isP) ld_tile(nb + 3 * TILE_B, Bl_, brow0, K, kc0 + i + 1, tid);
            CP_COMMIT();
            asm volatile("cp.async.wait_group 1;" ::: "memory");
        } else {
            asm volatile("cp.async.wait_group 0;" ::: "memory");
        }
        __syncthreads();

        const uint32_t Ah = T0 + cur * BUF_B;
        const uint32_t Bh = Ah + 2 * TILE_B;
        const uint32_t Bl = Ah + 3 * TILE_B;

        #pragma unroll
        for (int ks = 0; ks < 4; ks++) {
            const int kb = ks * 32;
            uint32_t ahi[2][4];
            #pragma unroll
            for (int mt = 0; mt < 2; mt++) {
                uint32_t ra = swz((uint32_t)(wm * 32 + mt * 16 + rowoff) * 128 + kb + coloff);
                ldsm4(ahi[mt], Ah + ra);
            }
            #pragma unroll
            for (int g = 0; g < 4; g++) {
                uint32_t rb = swz((uint32_t)(wn * 64 + g * 16 + rowoff) * 128 + kb + coloff);
                uint32_t bh[4], bl[4];
                ldsm4(bh, Bh + rb);
                if (isP) ldsm4(bl, Bl + rb);
                #pragma unroll
                for (int mt = 0; mt < 2; mt++) {
                    #pragma unroll
                    for (int sub = 0; sub < 2; sub++) {
                        float* c = acc[mt][g * 2 + sub];
                        if (isP) {
                            mma_fp(c, ahi[mt], bh[sub], bh[2 + sub]);
                            mma_fp(c, ahi[mt], bl[sub], bl[2 + sub]);
                        } else {
                            mma_bf(c, ahi[mt], bh[sub], bh[2 + sub]);
                        }
                    }
                }
            }
        }
        __syncthreads();
    }

    if (isP) {
        const int pz = bid >> 6;
        float* Cf = g_zb + (size_t)pz * N_ * H_;
        #pragma unroll
        for (int mt = 0; mt < 2; mt++) {
            #pragma unroll
            for (int nt = 0; nt < 8; nt++) {
                const int rl = wm * 32 + mt * 16 + (lane >> 2);
                const int cl = wn * 64 + nt * 8 + (lane & 3) * 2;
                const int r0 = arow0 + rl;
                const int cg = brow0 + cl;
                *(float2*)(Cf + (size_t)r0 * N_ + cg)       = make_float2(acc[mt][nt][0], acc[mt][nt][1]);
                *(float2*)(Cf + (size_t)(r0 + 8) * N_ + cg) = make_float2(acc[mt][nt][2], acc[mt][nt][3]);
            }
        }
    } else {
        // sigmoid + column-mean over rows 0..63 -> gmean
        float* gb = (float*)(smem + 1024);
        #pragma unroll
        for (int mt = 0; mt < 2; mt++) {
            #pragma unroll
            for (int nt = 0; nt < 8; nt++) {
                const int rl = wm * 32 + mt * 16 + (lane >> 2);
                const int cl = wn * 64 + nt * 8 + (lane & 3) * 2;
                float bb0 = sBias[cl], bb1 = sBias[cl + 1];
                gb[rl * 128 + cl]           = 1.0f / (1.0f + expf(-(acc[mt][nt][0] + bb0)));
                gb[rl * 128 + cl + 1]       = 1.0f / (1.0f + expf(-(acc[mt][nt][1] + bb1)));
                gb[(rl + 8) * 128 + cl]     = 1.0f / (1.0f + expf(-(acc[mt][nt][2] + bb0)));
                gb[(rl + 8) * 128 + cl + 1] = 1.0f / (1.0f + expf(-(acc[mt][nt][3] + bb1)));
            }
        }
        __syncthreads();
        if (tid < 128) {
            float s = 0.f;
            #pragma unroll 8
            for (int r = 0; r < 64; r++) s += gb[r * 128 + tid];
            g_gmean[brow0 + tid] = s * (1.0f / 64.0f);
        }
    }
}

// ---------------- k_mega3: M GEMM (128 CTAs) + bias_c (8) ----------------
__global__ __launch_bounds__(256, 1) void k_mega3(const float* __restrict__ nb2) {
    extern __shared__ __align__(1024) char smem[];
    uint32_t sb = smem_u32(smem);
    const int tid = threadIdx.x;
    const int wid = tid >> 5, lane = tid & 31;
    const int wm = wid >> 1, wn = wid & 1;
    const int bid = blockIdx.x;

    if (bid >= 128) {
        // cvec[h] = sum_m gmean[m]*ub[m]*W2t[h][m] + b2[h] ; 8 warps x 16 rows
        const int r0 = (bid - 128) * 128 + wid * 16;
        for (int rr = 0; rr < 16; rr++) {
            const int h = r0 + rr;
            const __half* pw = g_W2t16 + (size_t)h * N_;
            float s = 0.f;
            #pragma unroll 8
            for (int j = 0; j < 32; j++) {
                int m = j * 32 + lane;
                s += g_gmean[m] * g_u[m] * __half2float(pw[m]);
            }
            #pragma unroll
            for (int o = 16; o > 0; o >>= 1) s += __shfl_xor_sync(0xFFFFFFFFu, s, o);
            if (lane == 0) g_cvec[h] = s + nb2[h];
        }
        return;
    }

    const int mx = bid & 7, my = (bid >> 3) & 7, mz = bid >> 6;
    const int arow0 = my * 128, brow0 = mx * 128;
    const int kc0 = mz * 8;

    const uint32_t T0 = sb + 1024;
    float acc[2][8][4];
    #pragma unroll
    for (int i = 0; i < 2; i++)
        #pragma unroll
        for (int j = 0; j < 8; j++)
            #pragma unroll
            for (int l = 0; l < 4; l++) acc[i][j][l] = 0.f;

    const int mi = lane >> 3, li = lane & 7;
    const int rowoff = (mi & 1) * 8 + li;
    const int coloff = (mi >> 1) * 16;

    ld_tile(T0, g_W2t16, arow0, 1024, kc0, tid);
    ld_tile(T0 + 2 * TILE_B, g_P16h, brow0, 1024, kc0, tid);
    ld_tile(T0 + 3 * TILE_B, g_P16l, brow0, 1024, kc0, tid);
    CP_COMMIT();

    for (int i = 0; i < 8; i++) {
        const int cur = i & 1;
        if (i + 1 < 8) {
            uint32_t nb = T0 + (cur ^ 1) * BUF_B;
            ld_tile(nb, g_W2t16, arow0, 1024, kc0 + i + 1, tid);
            ld_tile(nb + 2 * TILE_B, g_P16h, brow0, 1024, kc0 + i + 1, tid);
            ld_tile(nb + 3 * TILE_B, g_P16l, brow0, 1024, kc0 + i + 1, tid);
            CP_COMMIT();
            asm volatile("cp.async.wait_group 1;" ::: "memory");
        } else {
            asm volatile("cp.async.wait_group 0;" ::: "memory");
        }
        __syncthreads();

        const uint32_t Ah = T0 + cur * BUF_B;
        const uint32_t Bh = Ah + 2 * TILE_B;
        const uint32_t Bl = Ah + 3 * TILE_B;

        #pragma unroll
        for (int ks = 0; ks < 4; ks++) {
            const int kb = ks * 32;
            uint32_t ahi[2][4];
            #pragma unroll
            for (int mt = 0; mt < 2; mt++) {
                uint32_t ra = swz((uint32_t)(wm * 32 + mt * 16 + rowoff) * 128 + kb + coloff);
                ldsm4(ahi[mt], Ah + ra);
            }
            #pragma unroll
            for (int g = 0; g < 4; g++) {
                uint32_t rb = swz((uint32_t)(wn * 64 + g * 16 + rowoff) * 128 + kb + coloff);
                uint32_t bh[4], bl[4];
                ldsm4(bh, Bh + rb);
                ldsm4(bl, Bl + rb);
                #pragma unroll
                for (int mt = 0; mt < 2; mt++) {
                    #pragma unroll
                    for (int sub = 0; sub < 2; sub++) {
                        float* c = acc[mt][g * 2 + sub];
                        mma_fp(c, ahi[mt], bh[sub], bh[2 + sub]);
                        mma_fp(c, ahi[mt], bl[sub], bl[2 + sub]);
                    }
                }
            }
        }
        __syncthreads();
    }

    float* Cf = g_zb + (size_t)mz * N_ * H_;
    #pragma unroll
    for (int mt = 0; mt < 2; mt++) {
        #pragma unroll
        for (int nt = 0; nt < 8; nt++) {
            const int rl = wm * 32 + mt * 16 + (lane >> 2);
            const int cl = wn * 64 + nt * 8 + (lane & 3) * 2;
            const int r0 = arow0 + rl;
            const int cg = brow0 + cl;
            *(float2*)(Cf + (size_t)r0 * H_ + cg)       = make_float2(acc[mt][nt][0], acc[mt][nt][1]);
            *(float2*)(Cf + (size_t)(r0 + 8) * H_ + cg) = make_float2(acc[mt][nt][2], acc[mt][nt][3]);
        }
    }
}

// ---------------- fp16 single-pass GEMM + fused residual/LayerNorm epilogue ----------------
#define FTILE_B 16384
#define FSTAGE_B (2 * FTILE_B)
#define FGEMM_SMEM (1024 + 3 * FSTAGE_B)

__global__ __launch_bounds__(256, 2) void fgemm(
    const __half* __restrict__ A,
    const __half* __restrict__ Bh,
    const float* __restrict__ bias,
    __half* __restrict__ Ch,
    const float* __restrict__ lw, const float* __restrict__ lb,
    float* __restrict__ out, int M, int Nn, int K)
{
    extern __shared__ __align__(1024) char smem[];
    uint32_t sb = smem_u32(smem);
    const int tid = threadIdx.x;
    const int wid = tid >> 5, lane = tid & 31;
    const int wm = wid >> 1, wn = wid & 1;
    const int bx = blockIdx.x, by = blockIdx.y;

    float* sBias = (float*)(smem + 512);
    if (tid < 128) sBias[tid] = bias[bx * 128 + tid];

    const uint32_t T0 = sb + 1024;
    const int NK = K >> 6;
    const int arow0 = by * 128, brow0 = bx * 128;

    float acc[2][8][4];
    #pragma unroll
    for (int i = 0; i < 2; i++)
        #pragma unroll
        for (int j = 0; j < 8; j++)
            #pragma unroll
            for (int l = 0; l < 4; l++) acc[i][j][l] = 0.f;

    const int mi = lane >> 3, li = lane & 7;
    const int rowoff = (mi & 1) * 8 + li;
    const int coloff = (mi >> 1) * 16;

    #pragma unroll
    for (int s = 0; s < 2; s++) {
        uint32_t st = T0 + s * FSTAGE_B;
        ld_tile(st,           A,  arow0, K, s, tid);
        ld_tile(st + FTILE_B, Bh, brow0, K, s, tid);
        CP_COMMIT();
    }

    for (int kc = 0; kc < NK; kc++) {
        if (kc == NK - 1) asm volatile("cp.async.wait_group 0;" ::: "memory");
        else              asm volatile("cp.async.wait_group 1;" ::: "memory");
        __syncthreads();

        if (kc + 2 < NK) {
            uint32_t st = T0 + ((kc + 2) % 3) * FSTAGE_B;
            ld_tile(st,           A,  arow0, K, kc + 2, tid);
            ld_tile(st + FTILE_B, Bh, brow0, K, kc + 2, tid);
            CP_COMMIT();
        }

        const uint32_t Sa = T0 + (kc % 3) * FSTAGE_B;
        const uint32_t Sh = Sa + FTILE_B;

        #pragma unroll
        for (int ks = 0; ks < 4; ks++) {
            const int kb = ks * 32;
            uint32_t a[2][4];
            #pragma unroll
            for (int mt = 0; mt < 2; mt++) {
                uint32_t ra = swz((uint32_t)(wm * 32 + mt * 16 + rowoff) * 128 + kb + coloff);
                ldsm4(a[mt], Sa + ra);
            }
            #pragma unroll
            for (int g = 0; g < 4; g++) {
                uint32_t rb = swz((uint32_t)(wn * 64 + g * 16 + rowoff) * 128 + kb + coloff);
                uint32_t bh[4];
                ldsm4(bh, Sh + rb);
                #pragma unroll
                for (int mt = 0; mt < 2; mt++) {
                    #pragma unroll
                    for (int sub = 0; sub < 2; sub++) {
                        mma_fp(acc[mt][g * 2 + sub], a[mt], bh[sub], bh[2 + sub]);
                    }
                }
            }
        }
    }

    #pragma unroll
    for (int mt = 0; mt < 2; mt++) {
        #pragma unroll
        for (int nt = 0; nt < 8; nt++) {
            const int r0 = by * 128 + wm * 32 + mt * 16 + (lane >> 2);
            const int cb = wn * 64 + nt * 8 + (lane & 3) * 2;
            const int cg = bx * 128 + cb;
            float bb0 = sBias[cb], bb1 = sBias[cb + 1];
            __half h0 = __float2half(acc[mt][nt][0] + bb0);
            __half h1 = __float2half(acc[mt][nt][1] + bb1);
            __half h2 = __float2half(acc[mt][nt][2] + bb0);
            __half h3 = __float2half(acc[mt][nt][3] + bb1);
            *(uint32_t*)(Ch + (size_t)r0 * Nn + cg)       = ((uint32_t)hfbits(h1) << 16) | hfbits(h0);
            *(uint32_t*)(Ch + (size_t)(r0 + 8) * Nn + cg) = ((uint32_t)hfbits(h3) << 16) | hfbits(h2);
        }
    }

    // ---- fused LN: last CTA of each row-block performs residual + LayerNorm ----
    __shared__ unsigned int sflag;
    __threadfence();
    __syncthreads();
    if (tid == 0) sflag = atomicAdd(&g_cnt[by], 1u);
    __syncthreads();
    if (sflag != 7) return;
    __threadfence();

    const float gw = 1.0f + tanhf(1.0f / 1024.0f);
    for (int r16 = 0; r16 < 16; r16++) {
        const size_t row = (size_t)by * 128 + wid * 16 + r16;
        const __half* ph = g_hA16 + row * H_;
        const __half* pm = Ch + row * H_;
        float v[32];
        float s = 0.f;
        #pragma unroll
        for (int j = 0; j < 8; j++) {
            int c = (j * 32 + lane) * 4;
            uint2 ha = *(const uint2*)(ph + c);
            uint2 ma = *(const uint2*)(pm + c);
            __half2 h01 = *reinterpret_cast<__half2*>(&ha.x);
            __half2 h23 = *reinterpret_cast<__half2*>(&ha.y);
            __half2 m01 = *reinterpret_cast<__half2*>(&ma.x);
            __half2 m23 = *reinterpret_cast<__half2*>(&ma.y);
            v[j * 4 + 0] = __low2float(h01) * gw + __low2float(m01);
            v[j * 4 + 1] = __high2float(h01) * gw + __high2float(m01);
            v[j * 4 + 2] = __low2float(h23) * gw + __low2float(m23);
            v[j * 4 + 3] = __high2float(h23) * gw + __high2float(m23);
            s += v[j * 4 + 0] + v[j * 4 + 1] + v[j * 4 + 2] + v[j * 4 + 3];
        }
        #pragma unroll
        for (int o = 16; o > 0; o >>= 1) s += __shfl_xor_sync(0xFFFFFFFFu, s, o);
        const float mu = s * (1.0f / H_);
        float ss = 0.f;
        #pragma unroll
        for (int j = 0; j < 32; j++) {
            v[j] -= mu;
            ss += v[j] * v[j];
        }
        #pragma unroll
        for (int o = 16; o > 0; o >>= 1) ss += __shfl_xor_sync(0xFFFFFFFFu, ss, o);
        const float rstd = rsqrtf(ss * (1.0f / H_) + 1e-5f);
        float* po = out + row * H_;
        #pragma unroll
        for (int j = 0; j < 8; j++) {
            int c = (j * 32 + lane) * 4;
            float4 w4 = *(const float4*)(lw + c);
            float4 b4 = *(const float4*)(lb + c);
            float4 o4;
            o4.x = v[j * 4 + 0] * rstd * w4.x + b4.x;
            o4.y = v[j * 4 + 1] * rstd * w4.y + b4.y;
            o4.z = v[j * 4 + 2] * rstd * w4.z + b4.z;
            o4.w = v[j * 4 + 3] * rstd * w4.w + b4.w;
            *(float4*)(po + c) = o4;
        }
    }
}

// ---------------- small kernels ----------------
// merged: pre (512 CTAs) + weight conversions (3072 CTAs)
__global__ __launch_bounds__(256) void k_preW(const float* __restrict__ h,
                                              const float* __restrict__ h2n_W,
                                              const float* __restrict__ n2h_W,
                                              const float* __restrict__ gate_W1,
                                              const float* __restrict__ gate_W2) {
    const int bid = blockIdx.x;
    const int tx = threadIdx.x & 31, ty = threadIdx.x >> 5;
    __shared__ float tt[32][33];
    if (bid < 512) {
        int b = bid >> 2;
        int hh = (bid & 3) * 256 + threadIdx.x;
        if (b >= 64) { g_hgHi[b * H_ + hh] = __float2bfloat16(0.f); return; }
        const float* p = h + (size_t)b * T_ * H_ + hh;
        __half* q = g_hA16 + (size_t)b * T_ * H_ + hh;
        float s = 0.f;
        #pragma unroll 4
        for (int t = 0; t < T_; t++) {
            float v = p[(size_t)t * H_];
            q[(size_t)t * H_] = __float2half(v);
            s += v;
        }
        float mean = s * (1.0f / T_);
        g_hgate[b * H_ + hh] = mean;
        g_hgHi[b * H_ + hh] = __float2bfloat16(mean);
        return;
    }
    const int wb = bid - 512;
    if (wb < 1024) {
        int i = wb * 256 + threadIdx.x;
        float4 v = ((const float4*)h2n_W)[i];
        __half h0 = __float2half(v.x), h1 = __float2half(v.y);
        __half h2 = __float2half(v.z), h3 = __float2half(v.w);
        uint2 hv;
        hv.x = ((uint32_t)hfbits(h1) << 16) | hfbits(h0);
        hv.y = ((uint32_t)hfbits(h3) << 16) | hfbits(h2);
        ((uint2*)g_W116)[i] = hv;
        return;
    }
    const float* W; int Rin, Cin, bx, by;
    if (wb < 2048) { W = n2h_W;   Rin = N_;   Cin = H_;   int l = wb - 1024; bx = l & 31; by = l >> 5; }
    else if (wb < 2560) { W = gate_W1; Rin = H_; Cin = HID_; int l = wb - 2048; bx = l & 15; by = l >> 4; }
    else { W = gate_W2; Rin = HID_; Cin = N_;  int l = wb - 2560; bx = l & 31; by = l >> 5; }
    int c0 = bx * 32, r0 = by * 32;
    #pragma unroll
    for (int i = 0; i < 4; i++)
        tt[ty + i * 8][tx] = W[(size_t)(r0 + ty + i * 8) * Cin + c0 + tx];
    __syncthreads();
    #pragma unroll
    for (int i = 0; i < 4; i++) {
        int oc = ty + i * 8;
        size_t o = (size_t)(c0 + oc) * Rin + r0 + tx;
        float v = tt[tx][oc];
        if (wb < 2048)      g_W2t16[o] = __float2half(v);
        else if (wb < 2560) g_G1h[o]   = __float2bfloat16(v);
        else                g_G2h[o]   = __float2bfloat16(v);
    }
}

__global__ void k_meanB() {
    int hh = blockIdx.x * blockDim.x + threadIdx.x;
    if (hh >= H_) return;
    if (hh < 128) g_cnt[hh] = 0u;   // reset fgemm row-block counters each invocation
    float s = 0.f;
    #pragma unroll
    for (int b = 0; b < B_; b++) s += g_hgate[b * H_ + hh];
    g_hmean[hh] = s * (1.0f / B_);
}

__global__ __launch_bounds__(256) void k_enorm(const float* __restrict__ E_dyn) {
    int i = blockIdx.x;
    __shared__ float red[256];
    float vals[4];
    float ss = 0.f;
    #pragma unroll
    for (int j = 0; j < 4; j++) {
        int hh = threadIdx.x + j * 256;
        float v = E_dyn[i * H_ + hh] + g_hmean[hh];
        vals[j] = v; ss += v * v;
    }
    red[threadIdx.x] = ss; __syncthreads();
    for (int off = 128; off > 0; off >>= 1) {
        if (threadIdx.x < off) red[threadIdx.x] += red[threadIdx.x + off];
        __syncthreads();
    }
    float inv = 1.0f / fmaxf(sqrtf(red[0]), 1e-12f);
    #pragma unroll
    for (int j = 0; j < 4; j++) {
        int hh = threadIdx.x + j * 256;
        g_Ehi[i * H_ + hh] = __float2bfloat16(vals[j] * inv);
    }
}

// combS (36 CTAs) + combG (32 CTAs)
__global__ __launch_bounds__(256) void k_combSG(const float* __restrict__ b1) {
    if (blockIdx.x >= 36) {
        const int base = (blockIdx.x - 36) * 2048;
        const float* z = g_zb + ZBG_OFF;
        #pragma unroll
        for (int k = 0; k < 8; k++) {
            int i = base + k * 256 + threadIdx.x;
            int n = i & (HID_ - 1);
            float v = z[i] + z[65536 + i] + z[2*65536 + i] + z[3*65536 + i] + b1[n];
            v = 0.5f * v * (1.0f + erff(v * 0.70710678118654752f));
            g_hidh[i] = __float2bfloat16(v);
        }
        return;
    }
    int t = blockIdx.x, i = 0;
    while (t >= 8 - i) { t -= 8 - i; i++; }
    const int by = i, bx = i + t;
    const float* z0 = g_zb + (size_t)blockIdx.x * 16384;
    const float* z1 = g_zb + (size_t)(36 + blockIdx.x) * 16384;
    __shared__ float sT[128][65];
    const int tid = threadIdx.x;
    #pragma unroll
    for (int half = 0; half < 2; half++) {
        const int r0 = half * 64;
        #pragma unroll 4
        for (int it = 0; it < 32; it++) {
            int idx = it * 256 + tid;
            int r = idx >> 7, c = idx & 127;
            float v = fmaxf(z0[(r0 + r) * 128 + c] + z1[(r0 + r) * 128 + c], 0.f);
            g_S[(size_t)(by * 128 + r0 + r) * N_ + bx * 128 + c] = v;
            sT[c][r] = v;
        }
        if (bx != by) {
            __syncthreads();
            #pragma unroll 4
            for (int it = 0; it < 32; it++) {
                int idx = it * 256 + tid;
                int c = idx >> 6, rr = idx & 63;
                g_S[(size_t)(bx * 128 + c) * N_ + by * 128 + r0 + rr] = sT[c][rr];
            }
            __syncthreads();
        }
    }
}

__global__ __launch_bounds__(256) void k_rowsum() {
    int i = blockIdx.x;
    __shared__ float red[256];
    float s = 0.f;
    for (int j = threadIdx.x; j < N_; j += 256) s += g_S[i * N_ + j];
    red[threadIdx.x] = s; __syncthreads();
    for (int off = 128; off > 0; off >>= 1) {
        if (threadIdx.x < off) red[threadIdx.x] += red[threadIdx.x + off];
        __syncthreads();
    }
    if (threadIdx.x == 0) g_rowsum[i] = 1.0f / (red[0] + 1e-6f);
}

// Abase elementwise (S symmetric, NO gmean): v = a*Ap + (1-a)*0.5*S*(ir[m]+ir[n]) -> fp16 split
__global__ void k_amix(const float* __restrict__ Ap, const float* __restrict__ alpha_raw) {
    int idx = blockIdx.x * blockDim.x + threadIdx.x;
    if (idx >= N_*N_) return;
    int m = idx >> 10, n = idx & 1023;
    float alpha = 1.0f / (1.0f + expf(-alpha_raw[0]));
    float v = alpha * Ap[idx] + (1.0f - alpha) * 0.5f * g_S[idx] * (g_rowsum[m] + g_rowsum[n]);
    __half h = __float2half(v);
    g_Am16h[idx] = h;
    g_Am16l[idx] = __float2half(v - __half2float(h));
}

// combine 2 split-K partials, apply gmean[m] -> fp16 hi/lo (P)
__global__ void k_combP() {
    int i = blockIdx.x * blockDim.x + threadIdx.x;
    if (i >= N_*H_) return;
    float v = (g_zb[i] + g_zb[(size_t)N_*H_ + i]) * g_gmean[i & 1023];
    __half h = __float2half(v);
    g_P16h[i] = h;
    g_P16l[i] = __float2half(v - __half2float(h));
}

// combine 2 split-K partials -> fp16 (Mcomb)
__global__ void k_combM() {
    int i = blockIdx.x * blockDim.x + threadIdx.x;
    if (i >= H_*H_) return;
    g_M16h[i] = __float2half(g_zb[i] + g_zb[(size_t)N_*H_ + i]);
}

// ---------------- launcher ----------------
extern "C" void kernel_launch(void* const* d_in, const int* in_sizes, int n_in,
                              void* d_out, int out_size) {
    const float* h_time    = (const float*)d_in[0];
    const float* A_pearson = (const float*)d_in[1];
    const float* E_dyn     = (const float*)d_in[2];
    const float* alpha_raw = (const float*)d_in[3];
    // d_in[4] = tau_raw : analytically eliminated (mean over softmax axis == 1/N)
    const float* gate_W1   = (const float*)d_in[5];
    const float* gate_b1   = (const float*)d_in[6];
    const float* gate_W2   = (const float*)d_in[7];
    const float* gate_b2   = (const float*)d_in[8];
    const float* h2n_W     = (const float*)d_in[9];
    const float* h2n_b     = (const float*)d_in[10];
    const float* n2h_W     = (const float*)d_in[11];
    const float* n2h_b     = (const float*)d_in[12];
    const float* ln_w      = (const float*)d_in[13];
    const float* ln_b      = (const float*)d_in[14];
    float* out = (float*)d_out;

    __half *p_hA16, *p_M16h, *p_msg16;
    float *p_cvec;
    cudaGetSymbolAddress((void**)&p_hA16, g_hA16);
    cudaGetSymbolAddress((void**)&p_M16h, g_M16h);
    cudaGetSymbolAddress((void**)&p_msg16, g_msg16);
    cudaGetSymbolAddress((void**)&p_cvec, g_cvec);

    cudaFuncSetAttribute(k_mega,  cudaFuncAttributeMaxDynamicSharedMemorySize, GEMM_SMEM);
    cudaFuncSetAttribute(k_mega2, cudaFuncAttributeMaxDynamicSharedMemorySize, GEMM_SMEM);
    cudaFuncSetAttribute(k_mega3, cudaFuncAttributeMaxDynamicSharedMemorySize, GEMM_SMEM);
    cudaFuncSetAttribute(fgemm,   cudaFuncAttributeMaxDynamicSharedMemorySize, FGEMM_SMEM);

    // 0: h_time pre (fp16 + h_gate) + all weight conversions
    k_preW<<<3584, 256>>>(h_time, h2n_W, n2h_W, gate_W1, gate_W2);
    // 1: batch-mean (+ LN counter reset)
    k_meanB<<<(H_ + 255) / 256, 256>>>();
    // 2: E row-normalize
    k_enorm<<<N_, 256>>>(E_dyn);
    // 3: S (36 tiles, split-K2) ∥ gate1 (split-K4)
    k_mega<<<dim3(52, 1, 2), 256, GEMM_SMEM>>>();
    // 4: combS (+mirror) ∥ combG (+gelu)
    k_combSG<<<68, 256>>>(gate_b1);
    // 5: row sums -> reciprocals
    k_rowsum<<<N_, 256>>>();
    // 6: Abase -> fp16 split (gmean deferred)
    k_amix<<<(N_*N_ + 255) / 256, 256>>>(A_pearson, alpha_raw);
    // 7: P GEMM (split-K2) ∥ gate2 (sigmoid+colmean->gmean) ∥ ub
    k_mega2<<<144, 256, GEMM_SMEM>>>(gate_b2, h2n_b);
    // 8: combine P partials * gmean -> fp16 split
    k_combP<<<(N_*H_ + 255) / 256, 256>>>();
    // 9: M GEMM (split-K2) ∥ bias_c (cvec)
    k_mega3<<<136, 256, GEMM_SMEM>>>(n2h_b);
    // 10: combine M partials -> fp16
    k_combM<<<(H_*H_ + 255) / 256, 256>>>();
    // 11: THE big GEMM + fused residual/LayerNorm epilogue
    fgemm<<<dim3(H_ / 128, BT_ / 128), 256, FGEMM_SMEM>>>(
        p_hA16, p_M16h, p_cvec, p_msg16, ln_w, ln_b, out, BT_, H_, H_);
}